// round 7
// baseline (speedup 1.0000x reference)
#include <cuda_runtime.h>
#include <math.h>

#define NSTEPS 4096
#define SMEMB 152000

__device__ float g_Ct[8192 * 128];
__device__ float g_pre[4096 * 128];
__device__ float g_b0[128];
__device__ float g_hb[3][2][128];
__device__ float g_ob[2][16];
__device__ int g_fl[3][4];
__device__ int g_fo;

__device__ __forceinline__ int ld_acq(const int* p) {
    int v; asm volatile("ld.global.acquire.gpu.s32 %0,[%1];" : "=r"(v) : "l"(p) : "memory"); return v;
}
__device__ __forceinline__ void st_rel(int* p, int v) {
    asm volatile("st.global.release.gpu.s32 [%0],%1;" :: "l"(p), "r"(v) : "memory");
}
__device__ __forceinline__ float ld_cg(const float* p) {
    float v; asm volatile("ld.global.cg.f32 %0,[%1];" : "=f"(v) : "l"(p) : "memory"); return v;
}
__device__ __forceinline__ void st_cg(float* p, float v) {
    asm volatile("st.global.cg.f32 [%0],%1;" :: "l"(p), "f"(v) : "memory");
}
__device__ __forceinline__ float sigm(float x) { return 1.0f / (1.0f + expf(-x)); }

// W col-major [col][row], pitch 128; 128x128; 512 threads.
__device__ __forceinline__ void mv128(const float* __restrict__ W, const float* __restrict__ x,
                                      float* __restrict__ part, int tid) {
    int rq = tid & 31, p = tid >> 5;
    const float* xp = x + p * 8;
    float4 acc = make_float4(0.f, 0.f, 0.f, 0.f);
#pragma unroll
    for (int k = 0; k < 8; k++) {
        float4 w = *(const float4*)(W + (p * 8 + k) * 128 + rq * 4);
        float xv = xp[k];
        acc.x += w.x * xv; acc.y += w.y * xv; acc.z += w.z * xv; acc.w += w.w * xv;
    }
    *(float4*)(part + p * 128 + rq * 4) = acc;
}
__device__ __forceinline__ float red16(const float* part, int r) {
    float s = 0.f;
#pragma unroll
    for (int p = 0; p < 16; p++) s += part[p * 128 + r];
    return s;
}

__global__ void k_init(const float* __restrict__ out0) {
    int t = threadIdx.x;
    if (t < 12) g_ob[1][t] = out0[t];
    else if (t < 16) g_ob[1][t] = 0.f;
    if (t == 0) g_fo = 1;
    if (t < 12) g_fl[t / 4][t % 4] = 0;
}

__global__ void k_bias0(const float* __restrict__ Wi2h, const float* __restrict__ bi2h,
                        const float* __restrict__ bs2i) {
    int h = threadIdx.x;
    float s = bi2h[h];
    for (int e = 0; e < 1024; e++) s += Wi2h[h * 1152 + e] * bs2i[e];
    g_b0[h] = s;
}

__global__ void __launch_bounds__(256) k_ct(const float* __restrict__ Wi2h,
                                            const float* __restrict__ Ws2i) {
    __shared__ float wa[32 * 128];
    int d0 = blockIdx.x * 64, dl = threadIdx.x & 63, hq = threadIdx.x >> 6;
    float acc[32];
#pragma unroll
    for (int k = 0; k < 32; k++) acc[k] = 0.f;
    for (int e0 = 0; e0 < 1024; e0 += 32) {
        __syncthreads();
        for (int i = threadIdx.x; i < 4096; i += 256)
            wa[i] = Wi2h[(i & 127) * 1152 + e0 + (i >> 7)];
        __syncthreads();
#pragma unroll 4
        for (int j = 0; j < 32; j++) {
            float s = Ws2i[(e0 + j) * 8192 + d0 + dl];
            const float* wr = wa + j * 128 + hq * 32;
#pragma unroll
            for (int k = 0; k < 32; k++) acc[k] += wr[k] * s;
        }
    }
    float* dst = g_Ct + (d0 + dl) * 128 + hq * 32;
#pragma unroll
    for (int k = 0; k < 32; k++) dst[k] = acc[k];
}

__global__ void __launch_bounds__(256) k_pre(const float* __restrict__ inputs) {
    __shared__ float in_s[16 * 128];
    int t0 = blockIdx.x * 16, h = threadIdx.x & 127, tq = threadIdx.x >> 7;
    float acc[8];
#pragma unroll
    for (int u = 0; u < 8; u++) acc[u] = 0.f;
    for (int d0 = 0; d0 < 8192; d0 += 128) {
        __syncthreads();
        for (int i = threadIdx.x; i < 2048; i += 256)
            in_s[i] = inputs[(t0 + (i >> 7)) * 8192 + d0 + (i & 127)];
        __syncthreads();
#pragma unroll 2
        for (int dd = 0; dd < 128; dd++) {
            float ctv = g_Ct[(d0 + dd) * 128 + h];
            const float* ip = in_s + tq * 1024 + dd * 0 + dd; // in_s[(tq*8+u)*128+dd]
#pragma unroll
            for (int u = 0; u < 8; u++) acc[u] += in_s[(tq * 8 + u) * 128 + dd] * ctv;
        }
    }
    float b = g_b0[h];
#pragma unroll
    for (int u = 0; u < 8; u++) g_pre[(t0 + tq * 8 + u) * 128 + h] = acc[u] + b;
}

// ---- persistent stages ----
__device__ void lstm_stage(float* sm, int l, int c, int incols,
                           const float* __restrict__ Wih, const float* __restrict__ Whh,
                           const float* __restrict__ bih, const float* __restrict__ bhh,
                           const float* __restrict__ hini, const float* __restrict__ cini,
                           float* dout, int out_size) {
    const int tid = threadIdx.x;
    float* wih = sm;            // 16384 (l>0 col-major; l==0 row-major pad13)
    float* whh = sm + 16384;    // 16384 col-major
    float* bias = sm + 32768;   // 128
    float* gacc = sm + 32896;   // 128
    float* gates = sm + 33024;  // 128
    float* part = sm + 33152;   // 2048
    float* xb = sm + 35200;     // 128
    float* xh = sm + 35328;     // 128
    float* cS = sm + 35456;     // 32
    float* hS = sm + 35488;     // 32

    if (incols == 128) {
        for (int i = tid; i < 16384; i += 512) {
            int j = i >> 7, lr = i & 127;
            int grow = (lr >> 5) * 128 + c * 32 + (lr & 31);
            wih[i] = Wih[grow * 128 + j];
        }
    } else {
        for (int i = tid; i < 128 * 12; i += 512) {
            int lr = i / 12, j = i - lr * 12;
            int grow = (lr >> 5) * 128 + c * 32 + (lr & 31);
            wih[lr * 13 + j] = Wih[grow * 12 + j];
        }
    }
    for (int i = tid; i < 16384; i += 512) {
        int j = i >> 7, lr = i & 127;
        int grow = (lr >> 5) * 128 + c * 32 + (lr & 31);
        whh[i] = Whh[grow * 128 + j];
    }
    if (tid < 128) {
        int grow = (tid >> 5) * 128 + c * 32 + (tid & 31);
        bias[tid] = bih[grow] + bhh[grow];
        xh[tid] = hini[tid];
    }
    if (tid < 32) { hS[tid] = hini[c * 32 + tid]; cS[tid] = cini[c * 32 + tid]; }
    __syncthreads();
    mv128(whh, xh, part, tid);
    __syncthreads();
    if (tid < 128) gacc[tid] = red16(part, tid);
    __syncthreads();

    const int* flin = (l == 0) ? &g_fo : g_fl[l - 1];
    int nfin = (l == 0) ? 1 : 4;
    const float(*gin)[16] = g_ob;
    for (int t = 0; t < NSTEPS; t++) {
        if (tid < nfin) { while (ld_acq(&flin[tid]) < t + 1) {} }
        __syncthreads();
        if (l == 0) {
            if (tid < 12) xb[tid] = ld_cg(&gin[(t + 1) & 1][tid]);
            __syncthreads();
            if (tid < 128) {
                const float* w = wih + tid * 13;
                float g = bias[tid] + gacc[tid];
#pragma unroll
                for (int j = 0; j < 12; j++) g += w[j] * xb[j];
                gates[tid] = g;
            }
        } else {
            if (tid < 128) xb[tid] = ld_cg(&g_hb[l - 1][t & 1][tid]);
            __syncthreads();
            mv128(wih, xb, part, tid);
            __syncthreads();
            if (tid < 128) gates[tid] = bias[tid] + gacc[tid] + red16(part, tid);
        }
        __syncthreads();
        if (tid < 32) {
            float cn = sigm(gates[32 + tid]) * cS[tid] + sigm(gates[tid]) * tanhf(gates[64 + tid]);
            float hn = sigm(gates[96 + tid]) * tanhf(cn);
            cS[tid] = cn; hS[tid] = hn;
            st_cg(&g_hb[l][t & 1][c * 32 + tid], hn);
        }
        __syncthreads();
        if (tid == 0) { __threadfence(); st_rel(&g_fl[l][c], t + 1); }
        // off-path: gacc = Whh @ h_l(t)
        if (tid < 4) { while (ld_acq(&g_fl[l][tid]) < t + 1) {} }
        __syncthreads();
        if (tid < 128) xh[tid] = ld_cg(&g_hb[l][t & 1][tid]);
        __syncthreads();
        mv128(whh, xh, part, tid);
        __syncthreads();
        if (tid < 128) gacc[tid] = red16(part, tid);
        __syncthreads();
    }
    if (out_size >= 49920 && tid < 32) {
        dout[49152 + l * 128 + c * 32 + tid] = hS[tid];
        dout[49536 + l * 128 + c * 32 + tid] = cS[tid];
    }
}

__device__ void tail_stage(float* sm, const float* __restrict__ Wi2h,
                           const float* __restrict__ Wh2h, const float* __restrict__ bh2h,
                           const float* __restrict__ Wh2o, const float* __restrict__ bh2o,
                           float* dout) {
    const int tid = threadIdx.x;
    float* wa = sm;             // 16384 i2h h-part col-major
    float* wb = sm + 16384;     // 16384 h2h col-major
    float* wo = sm + 32768;     // 1536 row-major
    float* bh = sm + 34304;     // 128
    float* bo = sm + 34432;     // 16
    float* h1 = sm + 34448;
    float* h2 = sm + 34576;
    float* part = sm + 34704;   // 2048
    float* xb = sm + 36752;     // 128
    float* pres = sm + 36880;   // 128

    for (int i = tid; i < 16384; i += 512) {
        int j = i >> 7, r = i & 127;
        wa[i] = Wi2h[r * 1152 + 1024 + j];
        wb[i] = Wh2h[r * 128 + j];
    }
    for (int i = tid; i < 1536; i += 512) wo[i] = Wh2o[i];
    if (tid < 128) bh[tid] = bh2h[tid];
    if (tid < 12) bo[tid] = bh2o[tid];
    __syncthreads();

    for (int t = 0; t < NSTEPS; t++) {
        if (tid < 4) { while (ld_acq(&g_fl[2][tid]) < t + 1) {} }
        __syncthreads();
        if (tid < 128) {
            xb[tid] = ld_cg(&g_hb[2][t & 1][tid]);
            pres[tid] = g_pre[t * 128 + tid];
        }
        __syncthreads();
        mv128(wa, xb, part, tid);
        __syncthreads();
        if (tid < 128) h1[tid] = tanhf(pres[tid] + red16(part, tid));
        __syncthreads();
        mv128(wb, h1, part, tid);
        __syncthreads();
        if (tid < 128) h2[tid] = fmaxf(bh[tid] + red16(part, tid), 0.f);
        __syncthreads();
        mv128(wb, h2, part, tid);
        __syncthreads();
        if (tid < 128) h1[tid] = fmaxf(bh[tid] + red16(part, tid), 0.f);
        __syncthreads();
        int w = tid >> 5, lane = tid & 31;
        if (w < 12) {
            const float* row = wo + w * 128;
            float s = row[lane] * h1[lane] + row[lane + 32] * h1[lane + 32] +
                      row[lane + 64] * h1[lane + 64] + row[lane + 96] * h1[lane + 96];
#pragma unroll
            for (int d = 16; d > 0; d >>= 1) s += __shfl_xor_sync(0xffffffffu, s, d);
            if (lane == 0) {
                float o = sigm(s + bo[w]);
                dout[t * 12 + w] = o;
                st_cg(&g_ob[t & 1][w], o);
            }
        }
        __syncthreads();
        if (tid == 0) { __threadfence(); st_rel(&g_fo, t + 2); }
        __syncthreads();
    }
}

__global__ void __launch_bounds__(512, 1) k_rnn(
    const float* Wih0, const float* Whh0, const float* bih0, const float* bhh0,
    const float* Wih1, const float* Whh1, const float* bih1, const float* bhh1,
    const float* Wih2, const float* Whh2, const float* bih2, const float* bhh2,
    const float* Wi2h, const float* Wh2h, const float* bh2h,
    const float* Wh2o, const float* bh2o,
    const float* h0, const float* c0, float* dout, int out_size) {
    extern __shared__ float sm[];
    int b = blockIdx.x;
    if (b < 12) {
        int l = b >> 2, c = b & 3;
        const float* Wih = (l == 0) ? Wih0 : (l == 1) ? Wih1 : Wih2;
        const float* Whh = (l == 0) ? Whh0 : (l == 1) ? Whh1 : Whh2;
        const float* bih = (l == 0) ? bih0 : (l == 1) ? bih1 : bih2;
        const float* bhh = (l == 0) ? bhh0 : (l == 1) ? bhh1 : bhh2;
        lstm_stage(sm, l, c, (l == 0) ? 12 : 128, Wih, Whh, bih, bhh,
                   h0 + l * 128, c0 + l * 128, dout, out_size);
    } else {
        tail_stage(sm, Wi2h, Wh2h, bh2h, Wh2o, bh2o, dout);
    }
}

extern "C" void kernel_launch(void* const* d_in, const int* in_sizes, int n_in,
                              void* d_out, int out_size) {
    const float* inputs = (const float*)d_in[0];
    const float* output0 = (const float*)d_in[1];
    const float* h0 = (const float*)d_in[2];
    const float* c0 = (const float*)d_in[3];
    const float* Ws2i = (const float*)d_in[4];
    const float* bs2i = (const float*)d_in[5];
    const float* Wi2h = (const float*)d_in[6];
    const float* bi2h = (const float*)d_in[7];
    const float* Wh2h = (const float*)d_in[8];
    const float* bh2h = (const float*)d_in[9];
    const float* Wh2o = (const float*)d_in[10];
    const float* bh2o = (const float*)d_in[11];
    float* out = (float*)d_out;

    static int once = 0;
    if (!once) {
        cudaFuncSetAttribute(k_rnn, cudaFuncAttributeMaxDynamicSharedMemorySize, SMEMB);
        once = 1;
    }
    k_init<<<1, 128>>>(output0);
    k_bias0<<<1, 128>>>(Wi2h, bi2h, bs2i);
    k_ct<<<128, 256>>>(Wi2h, Ws2i);
    k_pre<<<256, 256>>>(inputs);
    k_rnn<<<13, 512, SMEMB>>>(
        (const float*)d_in[12], (const float*)d_in[13], (const float*)d_in[14], (const float*)d_in[15],
        (const float*)d_in[16], (const float*)d_in[17], (const float*)d_in[18], (const float*)d_in[19],
        (const float*)d_in[20], (const float*)d_in[21], (const float*)d_in[22], (const float*)d_in[23],
        Wi2h, Wh2h, bh2h, Wh2o, bh2o, h0, c0, out, out_size);
}

// round 8
// speedup vs baseline: 1.9631x; 1.9631x over previous
#include <cuda_runtime.h>
#include <cuda_fp16.h>
#include <math.h>

#define NSTEPS 4096
#define SMEMB 184320
// byte offsets in dynamic smem (identical layout in every CTA so mapa offsets work)
#define B_BIN 0
#define B_SIB 8
#define XBUF 16      // 2*128 f32
#define SIBB 1040    // 2*128 f32
#define GATE 2064    // 512 f32
#define PART 4112    // 8*512 f32
#define HSO  20496   // 128 f32
#define CSO  21008   // 128 f32
#define BIASO 21520  // 512 f32
#define GACCO 23568  // 512 f32
#define WOFF 26144

__device__ float g_Ct[8192 * 128];
__device__ float g_pre[4096 * 128];
__device__ float g_b0[128];

__device__ __forceinline__ float sigm(float x) { return 1.0f / (1.0f + expf(-x)); }

__device__ __forceinline__ unsigned smem_u32(const void* p) {
    unsigned a; asm("{.reg .u64 t; cvta.to.shared.u64 t,%1; cvt.u32.u64 %0,t;}" : "=r"(a) : "l"(p)); return a;
}
__device__ __forceinline__ unsigned mapa_u32(unsigned l, unsigned rk) {
    unsigned r; asm("mapa.shared::cluster.u32 %0,%1,%2;" : "=r"(r) : "r"(l), "r"(rk)); return r;
}
__device__ __forceinline__ void mb_init(unsigned b, unsigned n) {
    asm volatile("mbarrier.init.shared.b64 [%0],%1;" :: "r"(b), "r"(n) : "memory");
}
__device__ __forceinline__ void bar_arm(unsigned b, unsigned tx) {
    asm volatile("mbarrier.arrive.expect_tx.shared.b64 _,[%0],%1;" :: "r"(b), "r"(tx) : "memory");
}
__device__ __forceinline__ void bar_wait(unsigned b, unsigned ph) {
    asm volatile("{.reg .pred P;\nW%=: mbarrier.try_wait.parity.acquire.cluster.shared::cta.b64 P,[%0],%1;\n@!P bra W%=;}\n"
                 :: "r"(b), "r"(ph) : "memory");
}
__device__ __forceinline__ void st_async_f(unsigned ra, float v, unsigned rb) {
    asm volatile("st.async.shared::cluster.mbarrier::complete_tx::bytes.b32 [%0],%1,[%2];"
                 :: "r"(ra), "r"(__float_as_uint(v)), "r"(rb) : "memory");
}
__device__ __forceinline__ void csync() {
    asm volatile("barrier.cluster.arrive.aligned;\nbarrier.cluster.wait.aligned;" ::: "memory");
}

// fp16 matvec: R rows x 128 cols, 512 threads. W stored as half2[c2*R + r] =
// (W[r][2c2], W[r][2c2+1]), c2 in [0,64). p=tid>>6 -> 8 col-pairs; rq=tid&63.
template<int R>
__device__ __forceinline__ void mvh(const __half2* __restrict__ W, const float* __restrict__ x,
                                    float* __restrict__ part, int tid) {
    constexpr int RP = R / 64;
    int rq = tid & 63, p = tid >> 6;
    float acc[RP];
#pragma unroll
    for (int i = 0; i < RP; i++) acc[i] = 0.f;
#pragma unroll
    for (int k = 0; k < 8; k++) {
        int c2 = p * 8 + k;
        float2 xf = *(const float2*)(x + 2 * c2);
        const __half2* wp = W + c2 * R + rq * RP;
#pragma unroll
        for (int i = 0; i < RP; i++) {
            float2 wf = __half22float2(wp[i]);
            acc[i] += wf.x * xf.x + wf.y * xf.y;
        }
    }
#pragma unroll
    for (int i = 0; i < RP; i++) part[p * R + rq * RP + i] = acc[i];
}
__device__ __forceinline__ float redp(const float* part, int R, int r) {
    float s = 0.f;
#pragma unroll
    for (int p = 0; p < 8; p++) s += part[p * R + r];
    return s;
}

// ---------- precompute ----------
__global__ void k_bias0(const float* __restrict__ Wi2h, const float* __restrict__ bi2h,
                        const float* __restrict__ bs2i) {
    int h = threadIdx.x;
    float s = bi2h[h];
    for (int e = 0; e < 1024; e++) s += Wi2h[h * 1152 + e] * bs2i[e];
    g_b0[h] = s;
}
__global__ void __launch_bounds__(256) k_ct(const float* __restrict__ Wi2h,
                                            const float* __restrict__ Ws2i) {
    __shared__ float wa[32 * 128];
    int d0 = blockIdx.x * 64, dl = threadIdx.x & 63, hq = threadIdx.x >> 6;
    float acc[32];
#pragma unroll
    for (int k = 0; k < 32; k++) acc[k] = 0.f;
    for (int e0 = 0; e0 < 1024; e0 += 32) {
        __syncthreads();
        for (int i = threadIdx.x; i < 4096; i += 256)
            wa[i] = Wi2h[(i & 127) * 1152 + e0 + (i >> 7)];
        __syncthreads();
#pragma unroll 4
        for (int j = 0; j < 32; j++) {
            float s = Ws2i[(e0 + j) * 8192 + d0 + dl];
            const float* wr = wa + j * 128 + hq * 32;
#pragma unroll
            for (int k = 0; k < 32; k++) acc[k] += wr[k] * s;
        }
    }
    float* dst = g_Ct + (d0 + dl) * 128 + hq * 32;
#pragma unroll
    for (int k = 0; k < 32; k++) dst[k] = acc[k];
}
__global__ void __launch_bounds__(256) k_pre(const float* __restrict__ inputs) {
    __shared__ float in_s[16 * 128];
    int t0 = blockIdx.x * 16, h = threadIdx.x & 127, tq = threadIdx.x >> 7;
    float acc[8];
#pragma unroll
    for (int u = 0; u < 8; u++) acc[u] = 0.f;
    for (int d0 = 0; d0 < 8192; d0 += 128) {
        __syncthreads();
        for (int i = threadIdx.x; i < 2048; i += 256)
            in_s[i] = inputs[(t0 + (i >> 7)) * 8192 + d0 + (i & 127)];
        __syncthreads();
#pragma unroll 2
        for (int dd = 0; dd < 128; dd++) {
            float ctv = g_Ct[(d0 + dd) * 128 + h];
#pragma unroll
            for (int u = 0; u < 8; u++) acc[u] += in_s[(tq * 8 + u) * 128 + dd] * ctv;
        }
    }
    float b = g_b0[h];
#pragma unroll
    for (int u = 0; u < 8; u++) g_pre[(t0 + tq * 8 + u) * 128 + h] = acc[u] + b;
}

// ---------- persistent cluster stages ----------
__device__ void lstm0(char* smc, unsigned sb, const float* Wih, const float* Whh,
                      const float* bih, const float* bhh, const float* out0,
                      const float* h0g, const float* c0g, float* dout, int out_size, int tid) {
    float* xb = (float*)(smc + XBUF);
    float* sib = (float*)(smc + SIBB);
    float* gates = (float*)(smc + GATE);
    float* part = (float*)(smc + PART);
    float* hS = (float*)(smc + HSO);
    float* cS = (float*)(smc + CSO);
    float* bias = (float*)(smc + BIASO);
    float* gacc = (float*)(smc + GACCO);
    float* wih = (float*)(smc + WOFF);                 // 512x12 fp32, pad 13
    __half2* whh = (__half2*)(smc + WOFF + 26624);     // 64 x 512 half2

    for (int i = tid; i < 512 * 12; i += 512) { int lr = i / 12, j = i - lr * 12; wih[lr * 13 + j] = Wih[lr * 12 + j]; }
    for (int i = tid; i < 64 * 512; i += 512) {
        int c2 = i >> 9, lr = i & 511;
        float2 a = *(const float2*)(Whh + lr * 128 + 2 * c2);
        whh[c2 * 512 + lr] = __floats2half2_rn(a.x, a.y);
    }
    bias[tid] = bih[tid] + bhh[tid];
    if (tid < 128) { sib[128 + tid] = h0g[tid]; hS[tid] = h0g[tid]; cS[tid] = c0g[tid]; }
    if (tid < 12) xb[tid] = out0[tid];
    if (tid == 0) mb_init(sb + B_BIN, 1);
    __syncthreads();
    mvh<512>(whh, sib + 128, part, tid);
    __syncthreads();
    gacc[tid] = redp(part, 512, tid);
    if (tid == 0) asm volatile("fence.mbarrier_init.release.cluster;" ::: "memory");
    csync();
    unsigned r1 = mapa_u32(sb, 1), r2 = mapa_u32(sb, 2);

    for (int t = 0; t < NSTEPS; t++) {
        int par = t & 1;
        if (t > 0) { if (tid == 0) { bar_arm(sb + B_BIN, 48); bar_wait(sb + B_BIN, (t - 1) & 1); } }
        __syncthreads();
        const float* x = (const float*)(smc + XBUF) + par * 16;
        {
            const float* w = wih + tid * 13;
            float g = bias[tid] + gacc[tid];
#pragma unroll
            for (int j = 0; j < 12; j++) g += w[j] * x[j];
            gates[tid] = g;
        }
        __syncthreads();
        if (tid < 128) {
            float cn = sigm(gates[128 + tid]) * cS[tid] + sigm(gates[tid]) * tanhf(gates[256 + tid]);
            float hn = sigm(gates[384 + tid]) * tanhf(cn);
            cS[tid] = cn; hS[tid] = hn;
            sib[par * 128 + tid] = hn;
            unsigned o4 = XBUF + par * 512 + tid * 4;
            st_async_f(r1 + o4, hn, r1 + B_BIN);
            st_async_f(r2 + o4, hn, r2 + B_BIN);
        }
        __syncthreads();
        if (t < NSTEPS - 1) {
            mvh<512>(whh, sib + par * 128, part, tid);
            __syncthreads();
            gacc[tid] = redp(part, 512, tid);
            __syncthreads();
        }
    }
    if (out_size >= 49920 && tid < 128) { dout[49152 + tid] = hS[tid]; dout[49536 + tid] = cS[tid]; }
    csync();
}

__device__ void lstm_mid(char* smc, unsigned sb, int l, int half, int sibrank,
                         int c0r, int c1r, int ncons,
                         const float* Wih, const float* Whh, const float* bih, const float* bhh,
                         const float* h0g, const float* c0g, float* dout, int out_size, int tid) {
    float* xb = (float*)(smc + XBUF);
    float* sib = (float*)(smc + SIBB);
    float* gates = (float*)(smc + GATE);
    float* part = (float*)(smc + PART);
    float* hS = (float*)(smc + HSO);
    float* cS = (float*)(smc + CSO);
    float* bias = (float*)(smc + BIASO);
    float* gacc = (float*)(smc + GACCO);
    __half2* wih = (__half2*)(smc + WOFF);
    __half2* whh = (__half2*)(smc + WOFF + 65536);
    const int U0 = half * 64;

    for (int i = tid; i < 64 * 256; i += 512) {
        int c2 = i >> 8, lr = i & 255;
        int grow = (lr >> 6) * 128 + U0 + (lr & 63);
        float2 a = *(const float2*)(Wih + grow * 128 + 2 * c2);
        float2 b = *(const float2*)(Whh + grow * 128 + 2 * c2);
        wih[c2 * 256 + lr] = __floats2half2_rn(a.x, a.y);
        whh[c2 * 256 + lr] = __floats2half2_rn(b.x, b.y);
    }
    if (tid < 256) { int grow = (tid >> 6) * 128 + U0 + (tid & 63); bias[tid] = bih[grow] + bhh[grow]; }
    if (tid < 128) sib[128 + tid] = h0g[tid];
    if (tid < 64) { hS[tid] = h0g[U0 + tid]; cS[tid] = c0g[U0 + tid]; }
    if (tid == 0) { mb_init(sb + B_BIN, 1); mb_init(sb + B_SIB, 1); }
    __syncthreads();
    mvh<256>(whh, sib + 128, part, tid);
    __syncthreads();
    if (tid < 256) gacc[tid] = redp(part, 256, tid);
    if (tid == 0) asm volatile("fence.mbarrier_init.release.cluster;" ::: "memory");
    csync();
    unsigned rs = mapa_u32(sb, sibrank);
    unsigned rc0 = mapa_u32(sb, c0r);
    unsigned rc1 = (ncons > 1) ? mapa_u32(sb, c1r) : 0;

    for (int t = 0; t < NSTEPS; t++) {
        int par = t & 1;
        if (tid == 0) { bar_arm(sb + B_BIN, 512); bar_wait(sb + B_BIN, par); }
        __syncthreads();
        mvh<256>(wih, xb + par * 128, part, tid);
        __syncthreads();
        if (tid < 256) gates[tid] = bias[tid] + gacc[tid] + redp(part, 256, tid);
        __syncthreads();
        if (tid < 64) {
            float cn = sigm(gates[64 + tid]) * cS[tid] + sigm(gates[tid]) * tanhf(gates[128 + tid]);
            float hn = sigm(gates[192 + tid]) * tanhf(cn);
            cS[tid] = cn; hS[tid] = hn;
            sib[par * 128 + U0 + tid] = hn;
            unsigned o4 = (U0 + tid) * 4;
            if (t < NSTEPS - 1) st_async_f(rs + SIBB + par * 512 + o4, hn, rs + B_SIB);
            st_async_f(rc0 + XBUF + par * 512 + o4, hn, rc0 + B_BIN);
            if (ncons > 1) st_async_f(rc1 + XBUF + par * 512 + o4, hn, rc1 + B_BIN);
        }
        if (t < NSTEPS - 1) {
            if (tid == 0) { bar_arm(sb + B_SIB, 256); bar_wait(sb + B_SIB, par); }
            __syncthreads();
            mvh<256>(whh, sib + par * 128, part, tid);
            __syncthreads();
            if (tid < 256) gacc[tid] = redp(part, 256, tid);
            __syncthreads();
        }
    }
    if (out_size >= 49920 && tid < 64) {
        dout[49152 + l * 128 + U0 + tid] = hS[tid];
        dout[49536 + l * 128 + U0 + tid] = cS[tid];
    }
    csync();
}

__device__ void tail(char* smc, unsigned sb, const float* Wi2h, const float* Wh2h,
                     const float* bh2h, const float* Wh2o, const float* bh2o,
                     float* dout, int tid) {
    float* xb = (float*)(smc + XBUF);
    float* h1 = (float*)(smc + GATE);
    float* h2 = (float*)(smc + GATE) + 128;
    float* part = (float*)(smc + PART);
    float* bh = (float*)(smc + BIASO);
    float* bo = (float*)(smc + BIASO) + 128;
    __half2* wa = (__half2*)(smc + WOFF);
    __half2* wb = (__half2*)(smc + WOFF + 32768);
    float* wo = (float*)(smc + WOFF + 65536);

    for (int i = tid; i < 64 * 128; i += 512) {
        int c2 = i >> 7, lr = i & 127;
        float2 a = *(const float2*)(Wi2h + lr * 1152 + 1024 + 2 * c2);
        float2 b = *(const float2*)(Wh2h + lr * 128 + 2 * c2);
        wa[c2 * 128 + lr] = __floats2half2_rn(a.x, a.y);
        wb[c2 * 128 + lr] = __floats2half2_rn(b.x, b.y);
    }
    for (int i = tid; i < 1536; i += 512) wo[i] = Wh2o[i];
    if (tid < 128) bh[tid] = bh2h[tid];
    if (tid < 12) bo[tid] = bh2o[tid];
    if (tid == 0) { mb_init(sb + B_BIN, 1); asm volatile("fence.mbarrier_init.release.cluster;" ::: "memory"); }
    __syncthreads();
    csync();
    unsigned r0 = mapa_u32(sb, 0);

    for (int t = 0; t < NSTEPS; t++) {
        int par = t & 1;
        float pf = (tid < 128) ? g_pre[t * 128 + tid] : 0.f;  // prefetch overlaps wait
        if (tid == 0) { bar_arm(sb + B_BIN, 512); bar_wait(sb + B_BIN, par); }
        __syncthreads();
        mvh<128>(wa, xb + par * 128, part, tid);
        __syncthreads();
        if (tid < 128) h1[tid] = tanhf(pf + redp(part, 128, tid));
        __syncthreads();
        mvh<128>(wb, h1, part, tid);
        __syncthreads();
        if (tid < 128) h2[tid] = fmaxf(bh[tid] + redp(part, 128, tid), 0.f);
        __syncthreads();
        mvh<128>(wb, h2, part, tid);
        __syncthreads();
        if (tid < 128) h1[tid] = fmaxf(bh[tid] + redp(part, 128, tid), 0.f);
        __syncthreads();
        int w = tid >> 5, lane = tid & 31;
        if (w < 12) {
            const float* row = wo + w * 128;
            float s = row[lane] * h1[lane] + row[lane + 32] * h1[lane + 32] +
                      row[lane + 64] * h1[lane + 64] + row[lane + 96] * h1[lane + 96];
#pragma unroll
            for (int d = 16; d > 0; d >>= 1) s += __shfl_xor_sync(0xffffffffu, s, d);
            if (lane == 0) {
                float o = sigm(s + bo[w]);
                dout[t * 12 + w] = o;
                if (t < NSTEPS - 1)
                    st_async_f(r0 + XBUF + ((t + 1) & 1) * 64 + w * 4, o, r0 + B_BIN);
            }
        }
        __syncthreads();
    }
    csync();
}

__global__ void __launch_bounds__(512, 1) __cluster_dims__(6, 1, 1) k_rnn(
    const float* Wih0, const float* Whh0, const float* bih0, const float* bhh0,
    const float* Wih1, const float* Whh1, const float* bih1, const float* bhh1,
    const float* Wih2, const float* Whh2, const float* bih2, const float* bhh2,
    const float* Wi2h, const float* Wh2h, const float* bh2h,
    const float* Wh2o, const float* bh2o, const float* out0,
    const float* h0, const float* c0, float* dout, int out_size) {
    extern __shared__ char smc[];
    unsigned sb = smem_u32(smc);
    int r = blockIdx.x, tid = threadIdx.x;
    if (r == 0)
        lstm0(smc, sb, Wih0, Whh0, bih0, bhh0, out0, h0, c0, dout, out_size, tid);
    else if (r <= 2)
        lstm_mid(smc, sb, 1, r - 1, 3 - r, 3, 4, 2, Wih1, Whh1, bih1, bhh1,
                 h0 + 128, c0 + 128, dout, out_size, tid);
    else if (r <= 4)
        lstm_mid(smc, sb, 2, r - 3, 7 - r, 5, 5, 1, Wih2, Whh2, bih2, bhh2,
                 h0 + 256, c0 + 256, dout, out_size, tid);
    else
        tail(smc, sb, Wi2h, Wh2h, bh2h, Wh2o, bh2o, dout, tid);
}

extern "C" void kernel_launch(void* const* d_in, const int* in_sizes, int n_in,
                              void* d_out, int out_size) {
    const float* inputs = (const float*)d_in[0];
    const float* output0 = (const float*)d_in[1];
    const float* h0 = (const float*)d_in[2];
    const float* c0 = (const float*)d_in[3];
    const float* Ws2i = (const float*)d_in[4];
    const float* bs2i = (const float*)d_in[5];
    const float* Wi2h = (const float*)d_in[6];
    const float* bi2h = (const float*)d_in[7];
    const float* Wh2h = (const float*)d_in[8];
    const float* bh2h = (const float*)d_in[9];
    const float* Wh2o = (const float*)d_in[10];
    const float* bh2o = (const float*)d_in[11];
    float* out = (float*)d_out;

    static int once = 0;
    if (!once) {
        cudaFuncSetAttribute(k_rnn, cudaFuncAttributeMaxDynamicSharedMemorySize, SMEMB);
        once = 1;
    }
    k_bias0<<<1, 128>>>(Wi2h, bi2h, bs2i);
    k_ct<<<128, 256>>>(Wi2h, Ws2i);
    k_pre<<<256, 256>>>(inputs);
    k_rnn<<<6, 512, SMEMB>>>(
        (const float*)d_in[12], (const float*)d_in[13], (const float*)d_in[14], (const float*)d_in[15],
        (const float*)d_in[16], (const float*)d_in[17], (const float*)d_in[18], (const float*)d_in[19],
        (const float*)d_in[20], (const float*)d_in[21], (const float*)d_in[22], (const float*)d_in[23],
        Wi2h, Wh2h, bh2h, Wh2o, bh2o, output0, h0, c0, out, out_size);
}